// round 2
// baseline (speedup 1.0000x reference)
#include <cuda_runtime.h>
#include <math.h>
#include <stdint.h>

#define NB 8
#define NTOK 1024
#define CC2 512
#define KVD 1792
#define NH 4
#define NMAPS (NB*NH)          // 32
#define MAPELEMS (CC2*KVD)     // 917504
#define NCHUNK 28              // MAPELEMS / 32768
#define NPART (NMAPS*NCHUNK)   // 896

// ---------------- scratch (device globals: allocation-guard safe) ----------
__device__ __align__(128) float g_X   [NB*NTOK*KVD];     // LN(concat)       58.7MB
__device__ __align__(128) float g_cx2 [NB*NTOK*CC2];     // LN(emb2)
__device__ __align__(128) float g_G   [NB*CC2*KVD];      // cx2^T X per b
__device__ __align__(128) float g_T   [NMAPS*CC2*KVD];   // Wq^T G           117MB
__device__ __align__(128) float g_S   [NMAPS*CC2*KVD];   // scores / probs   117MB
__device__ __align__(128) float g_M   [NB*KVD*CC2];      // (1/H) sum_h Wv probs^T
__device__ __align__(128) float g_ctx [NB*NTOK*CC2];
__device__ __align__(128) float g_res [NB*NTOK*CC2];     // emb2 + o
__device__ __align__(128) float g_x2  [NB*NTOK*CC2];     // LN for FFN
__device__ __align__(128) float g_h1  [NB*NTOK*CC2*4];   // fc1+gelu         67MB
__device__ __align__(128) float g_part[NPART*2];
__device__ __align__(128) float g_stats[NMAPS*2];        // mean, rstd per map

// ---------------- block reduce -------------------------------------------
__device__ __forceinline__ float blockReduceSum(float v, float* sbuf) {
    #pragma unroll
    for (int o = 16; o > 0; o >>= 1) v += __shfl_down_sync(0xffffffffu, v, o);
    int lane = threadIdx.x & 31, w = threadIdx.x >> 5;
    if (lane == 0) sbuf[w] = v;
    __syncthreads();
    float tot = 0.f;
    #pragma unroll
    for (int i = 0; i < 8; i++) tot += sbuf[i];
    __syncthreads();
    return tot;
}

// ---------------- LN kernels ---------------------------------------------
__global__ void __launch_bounds__(256) ln_all_kernel(
    const float* __restrict__ e1, const float* __restrict__ e2, const float* __restrict__ e3,
    const float* __restrict__ g1, const float* __restrict__ b1,
    const float* __restrict__ ga, const float* __restrict__ ba,
    float* __restrict__ X, float* __restrict__ cx2)
{
    __shared__ float xs[KVD];
    __shared__ float red[8];
    int tok = blockIdx.x, t = threadIdx.x;
    const float* p1 = e1 + (size_t)tok * 256;
    const float* p2 = e2 + (size_t)tok * 512;
    const float* p3 = e3 + (size_t)tok * 1024;
    xs[t] = p1[t];
    xs[256 + t] = p2[t];
    xs[512 + t] = p2[256 + t];
    #pragma unroll
    for (int i = 0; i < 4; i++) xs[768 + t + i * 256] = p3[t + i * 256];
    __syncthreads();
    float s = 0.f, ss = 0.f, s2 = 0.f, ss2 = 0.f;
    for (int i = t; i < KVD; i += 256) { float x = xs[i]; s += x; ss += x * x; }
    for (int i = t; i < 512; i += 256) { float x = xs[256 + i]; s2 += x; ss2 += x * x; }
    s  = blockReduceSum(s,  red);
    ss = blockReduceSum(ss, red);
    s2 = blockReduceSum(s2, red);
    ss2= blockReduceSum(ss2,red);
    float m  = s  * (1.f / KVD), r  = rsqrtf(ss  * (1.f / KVD) - m  * m  + 1e-6f);
    float m2 = s2 * (1.f / 512.f), r2 = rsqrtf(ss2 * (1.f / 512.f) - m2 * m2 + 1e-6f);
    float* Xo = X + (size_t)tok * KVD;
    float* co = cx2 + (size_t)tok * 512;
    for (int i = t; i < KVD; i += 256) Xo[i] = (xs[i] - m) * r * ga[i] + ba[i];
    for (int i = t; i < 512; i += 256) co[i] = (xs[256 + i] - m2) * r2 * g1[i] + b1[i];
}

__global__ void __launch_bounds__(256) ln512_kernel(
    const float* __restrict__ in, const float* __restrict__ g, const float* __restrict__ b,
    float* __restrict__ out)
{
    __shared__ float red[8];
    int tok = blockIdx.x, t = threadIdx.x;
    const float* p = in + (size_t)tok * 512;
    float x0 = p[t], x1 = p[t + 256];
    float s = blockReduceSum(x0 + x1, red);
    float ss = blockReduceSum(x0 * x0 + x1 * x1, red);
    float m = s * (1.f / 512.f);
    float r = rsqrtf(ss * (1.f / 512.f) - m * m + 1e-6f);
    float* o = out + (size_t)tok * 512;
    o[t] = (x0 - m) * r * g[t] + b[t];
    o[t + 256] = (x1 - m) * r * g[t + 256] + b[t + 256];
}

// ---------------- instance-norm stats (deterministic 2-stage) -------------
__global__ void __launch_bounds__(256) stats_part_kernel(const float* __restrict__ S,
                                                         float* __restrict__ part)
{
    __shared__ float red[8];
    int bx = blockIdx.x, t = threadIdx.x;
    const float4* p = (const float4*)(S + (size_t)bx * 32768);
    float s = 0.f, ss = 0.f;
    for (int i = t; i < 8192; i += 256) {
        float4 v = p[i];
        s  += v.x + v.y + v.z + v.w;
        ss += v.x * v.x + v.y * v.y + v.z * v.z + v.w * v.w;
    }
    s = blockReduceSum(s, red);
    ss = blockReduceSum(ss, red);
    if (t == 0) { part[bx * 2] = s; part[bx * 2 + 1] = ss; }
}

__global__ void stats_final_kernel(const float* __restrict__ part, float* __restrict__ stats)
{
    int m = threadIdx.x;
    if (m < NMAPS) {
        float s = 0.f, ss = 0.f;
        for (int c = 0; c < NCHUNK; c++) {
            s  += part[(m * NCHUNK + c) * 2];
            ss += part[(m * NCHUNK + c) * 2 + 1];
        }
        float inv = 1.f / (float)MAPELEMS;
        float mean = s * inv;
        float var = ss * inv - mean * mean;
        stats[2 * m] = mean;
        stats[2 * m + 1] = rsqrtf(var + 1e-5f);
    }
}

// ---------------- softmax over KV (IN mean cancels; only rstd needed) -----
__global__ void __launch_bounds__(256) softmax_kernel(float* __restrict__ S,
                                                      const float* __restrict__ stats)
{
    __shared__ float red[8];
    int row = blockIdx.x, t = threadIdx.x;
    int map = row >> 9;
    float r = stats[map * 2 + 1];
    float* p = S + (size_t)row * KVD;
    float v[7];
    float mx = -1e30f;
    #pragma unroll
    for (int j = 0; j < 7; j++) { v[j] = p[t + j * 256] * r; mx = fmaxf(mx, v[j]); }
    #pragma unroll
    for (int o = 16; o > 0; o >>= 1) mx = fmaxf(mx, __shfl_xor_sync(0xffffffffu, mx, o));
    int lane = t & 31, w = t >> 5;
    if (lane == 0) red[w] = mx;
    __syncthreads();
    float bm = red[0];
    #pragma unroll
    for (int i = 1; i < 8; i++) bm = fmaxf(bm, red[i]);
    __syncthreads();
    float s = 0.f;
    #pragma unroll
    for (int j = 0; j < 7; j++) { v[j] = expf(v[j] - bm); s += v[j]; }
    s = blockReduceSum(s, red);
    float inv = 1.f / s;
    #pragma unroll
    for (int j = 0; j < 7; j++) p[t + j * 256] = v[j] * inv;
}

// ---------------- generic batched tiled GEMM ------------------------------
// C[z] = alpha * sum_seg opA(A[za]) @ opB(B[zb]) (+epilogue)
// OPA/OPB: 0 = row-major [M,K]/[K,N]; 1 = stored transposed [K,M]/[N,K]
// EPI: 0 store; 1 gelu(acc+bias); 2 acc+bias?+add
struct GemmP {
    const float* A; const float* B; float* C;
    int M, N, K, lda, ldb, ldc;
    long sA, sB, sC;
    int aSel, bSel;            // 0: z, 1: z%4, 2: z/4
    int nseg; long segA, segB;
    float alpha;
    const float* bias;
    const float* add; int ldAdd; long sAdd;
};

__device__ __forceinline__ int selIdx(int z, int sel) {
    return sel == 0 ? z : (sel == 1 ? (z & 3) : (z >> 2));
}

template <int OPA, int OPB, int EPI>
__global__ void __launch_bounds__(256) gemm_kernel(GemmP p)
{
    __shared__ float As[16][64];
    __shared__ float Bs[16][64];
    int z = blockIdx.z;
    const float* A = p.A + (long)selIdx(z, p.aSel) * p.sA;
    const float* B = p.B + (long)selIdx(z, p.bSel) * p.sB;
    float* C = p.C + (long)z * p.sC;
    int m0 = blockIdx.y * 64, n0 = blockIdx.x * 64;
    int t = threadIdx.x;
    float acc[4][4] = {};
    int tmL = (t & 15) << 2, tnL = (t >> 4) << 2;

    for (int sgi = 0; sgi < p.nseg; sgi++, A += p.segA, B += p.segB) {
        for (int k0 = 0; k0 < p.K; k0 += 16) {
            if (OPA == 0) {             // A[m][k]
                int m = t >> 2, kq = (t & 3) << 2;
                float4 v = *(const float4*)&A[(size_t)(m0 + m) * p.lda + k0 + kq];
                As[kq + 0][m] = v.x; As[kq + 1][m] = v.y;
                As[kq + 2][m] = v.z; As[kq + 3][m] = v.w;
            } else {                    // A stored [k][m]
                int kk = t >> 4, mq = (t & 15) << 2;
                *(float4*)&As[kk][mq] = *(const float4*)&A[(size_t)(k0 + kk) * p.lda + m0 + mq];
            }
            if (OPB == 0) {             // B[k][n]
                int kk = t >> 4, nq = (t & 15) << 2;
                *(float4*)&Bs[kk][nq] = *(const float4*)&B[(size_t)(k0 + kk) * p.ldb + n0 + nq];
            } else {                    // B stored [n][k]
                int n = t >> 2, kq = (t & 3) << 2;
                float4 v = *(const float4*)&B[(size_t)(n0 + n) * p.ldb + k0 + kq];
                Bs[kq + 0][n] = v.x; Bs[kq + 1][n] = v.y;
                Bs[kq + 2][n] = v.z; Bs[kq + 3][n] = v.w;
            }
            __syncthreads();
            #pragma unroll
            for (int kk = 0; kk < 16; kk++) {
                float4 a = *(const float4*)&As[kk][tmL];
                float4 b = *(const float4*)&Bs[kk][tnL];
                float av[4] = {a.x, a.y, a.z, a.w};
                float bv[4] = {b.x, b.y, b.z, b.w};
                #pragma unroll
                for (int i = 0; i < 4; i++)
                    #pragma unroll
                    for (int j = 0; j < 4; j++)
                        acc[i][j] += av[i] * bv[j];
            }
            __syncthreads();
        }
    }

    int tm = m0 + tmL, tn = n0 + tnL;
    #pragma unroll
    for (int i = 0; i < 4; i++) {
        float vals[4];
        #pragma unroll
        for (int j = 0; j < 4; j++) {
            float v = p.alpha * acc[i][j];
            if (EPI >= 1 && p.bias) v += p.bias[tn + j];
            if (EPI == 1) v = 0.5f * v * (1.f + erff(v * 0.70710678118654752f));
            if (EPI == 2) v += p.add[(long)z * p.sAdd + (size_t)(tm + i) * p.ldAdd + tn + j];
            vals[j] = v;
        }
        *(float4*)&C[(size_t)(tm + i) * p.ldc + tn] =
            make_float4(vals[0], vals[1], vals[2], vals[3]);
    }
}

// ---------------- host launcher -------------------------------------------
static inline GemmP mkP(const float* A, const float* B, float* C,
                        int M, int N, int K, int lda, int ldb, int ldc,
                        long sA, long sB, long sC, int aSel, int bSel,
                        int nseg, long segA, long segB, float alpha,
                        const float* bias, const float* add, int ldAdd, long sAdd)
{
    GemmP p; p.A = A; p.B = B; p.C = C; p.M = M; p.N = N; p.K = K;
    p.lda = lda; p.ldb = ldb; p.ldc = ldc; p.sA = sA; p.sB = sB; p.sC = sC;
    p.aSel = aSel; p.bSel = bSel; p.nseg = nseg; p.segA = segA; p.segB = segB;
    p.alpha = alpha; p.bias = bias; p.add = add; p.ldAdd = ldAdd; p.sAdd = sAdd;
    return p;
}

extern "C" void kernel_launch(void* const* d_in, const int* in_sizes, int n_in,
                              void* d_out, int out_size)
{
    const float* emb1   = (const float*)d_in[0];
    const float* emb2   = (const float*)d_in[1];
    const float* emb3   = (const float*)d_in[2];
    const float* Wq     = (const float*)d_in[3];
    const float* Wk     = (const float*)d_in[4];
    const float* Wv     = (const float*)d_in[5];
    const float* Wout   = (const float*)d_in[6];
    const float* ln1_g  = (const float*)d_in[7];
    const float* ln1_b  = (const float*)d_in[8];
    const float* lnall_g= (const float*)d_in[9];
    const float* lnall_b= (const float*)d_in[10];
    const float* lnffn_g= (const float*)d_in[11];
    const float* lnffn_b= (const float*)d_in[12];
    const float* fc1_w  = (const float*)d_in[13];
    const float* fc1_b  = (const float*)d_in[14];
    const float* fc2_w  = (const float*)d_in[15];
    const float* fc2_b  = (const float*)d_in[16];
    float* out = (float*)d_out;

    float *X, *cx2, *G, *T, *S, *Mm, *ctx, *res, *x2, *h1, *part, *stats;
    cudaGetSymbolAddress((void**)&X,    g_X);
    cudaGetSymbolAddress((void**)&cx2,  g_cx2);
    cudaGetSymbolAddress((void**)&G,    g_G);
    cudaGetSymbolAddress((void**)&T,    g_T);
    cudaGetSymbolAddress((void**)&S,    g_S);
    cudaGetSymbolAddress((void**)&Mm,   g_M);
    cudaGetSymbolAddress((void**)&ctx,  g_ctx);
    cudaGetSymbolAddress((void**)&res,  g_res);
    cudaGetSymbolAddress((void**)&x2,   g_x2);
    cudaGetSymbolAddress((void**)&h1,   g_h1);
    cudaGetSymbolAddress((void**)&part, g_part);
    cudaGetSymbolAddress((void**)&stats,g_stats);

    const long MAPSZ = (long)CC2 * KVD;   // 917504
    const float inv_sqrt_kv = 1.f / sqrtf((float)KVD);

    // 1. LayerNorms (concat fused)
    ln_all_kernel<<<NB * NTOK, 256>>>(emb1, emb2, emb3, ln1_g, ln1_b,
                                      lnall_g, lnall_b, X, cx2);

    // 2. G[b] = cx2[b]^T @ X[b]   [512 x 1792], K = 1024 tokens
    gemm_kernel<1, 0, 0><<<dim3(28, 8, 8), 256>>>(
        mkP(cx2, X, G, 512, KVD, NTOK, 512, KVD, KVD,
            (long)NTOK * 512, (long)NTOK * KVD, MAPSZ, 0, 0,
            1, 0, 0, 1.f, nullptr, nullptr, 0, 0));

    // 3. T[b,h] = Wq[h]^T @ G[b]   [512 x 1792], K = 512
    gemm_kernel<1, 0, 0><<<dim3(28, 8, 32), 256>>>(
        mkP(Wq, G, T, 512, KVD, 512, 512, KVD, KVD,
            (long)512 * 512, MAPSZ, MAPSZ, 1, 2,
            1, 0, 0, 1.f, nullptr, nullptr, 0, 0));

    // 4. S[b,h] = (1/sqrt(KV)) T[b,h] @ Wk[h]   [512 x 1792], K = 1792
    gemm_kernel<0, 0, 0><<<dim3(28, 8, 32), 256>>>(
        mkP(T, Wk, S, 512, KVD, KVD, KVD, KVD, KVD,
            MAPSZ, (long)KVD * KVD, MAPSZ, 0, 1,
            1, 0, 0, inv_sqrt_kv, nullptr, nullptr, 0, 0));

    // 5. InstanceNorm stats (mean cancels in softmax; need only rstd)
    stats_part_kernel<<<NPART, 256>>>(S, part);
    stats_final_kernel<<<1, 32>>>(part, stats);

    // 6. probs = softmax(rstd * S) over KV, in place
    softmax_kernel<<<NMAPS * 512, 256>>>(S, stats);

    // 7. M[b] = (1/H) sum_h Wv[h] @ probs[b,h]^T   [1792 x 512], K = 1792 x 4 segs
    gemm_kernel<0, 1, 0><<<dim3(8, 28, 8), 256>>>(
        mkP(Wv, S, Mm, KVD, 512, KVD, KVD, KVD, 512,
            0, 4 * MAPSZ, (long)KVD * 512, 0, 0,
            4, (long)KVD * KVD, MAPSZ, 0.25f, nullptr, nullptr, 0, 0));

    // 8. ctx[b] = X[b] @ M[b]   [1024 x 512], K = 1792
    gemm_kernel<0, 0, 0><<<dim3(8, 16, 8), 256>>>(
        mkP(X, Mm, ctx, NTOK, 512, KVD, KVD, 512, 512,
            (long)NTOK * KVD, (long)KVD * 512, (long)NTOK * 512, 0, 0,
            1, 0, 0, 1.f, nullptr, nullptr, 0, 0));

    // 9. res = ctx @ Wout + emb2   [8192 x 512], K = 512
    gemm_kernel<0, 0, 2><<<dim3(8, 128, 1), 256>>>(
        mkP(ctx, Wout, res, NB * NTOK, 512, 512, 512, 512, 512,
            0, 0, 0, 0, 0, 1, 0, 0, 1.f, nullptr, emb2, 512, 0));

    // 10. x2 = LN(res) with lnffn
    ln512_kernel<<<NB * NTOK, 256>>>(res, lnffn_g, lnffn_b, x2);

    // 11. h1 = gelu(x2 @ fc1_w + fc1_b)   [8192 x 2048], K = 512
    gemm_kernel<0, 0, 1><<<dim3(32, 128, 1), 256>>>(
        mkP(x2, fc1_w, h1, NB * NTOK, 2048, 512, 512, 2048, 2048,
            0, 0, 0, 0, 0, 1, 0, 0, 1.f, fc1_b, nullptr, 0, 0));

    // 12. out = h1 @ fc2_w + fc2_b + res   [8192 x 512], K = 2048
    gemm_kernel<0, 0, 2><<<dim3(8, 128, 1), 256>>>(
        mkP(h1, fc2_w, out, NB * NTOK, 512, 2048, 2048, 512, 512,
            0, 0, 0, 0, 0, 1, 0, 0, 1.f, fc2_b, res, 512, 0));
}

// round 5
// speedup vs baseline: 4.1065x; 4.1065x over previous
#include <cuda_runtime.h>
#include <math.h>
#include <stdint.h>

#define NB 8
#define NTOK 1024
#define CC2 512
#define KVD 1792
#define NH 4
#define NMAPS (NB*NH)          // 32
#define MAPELEMS (CC2*KVD)     // 917504
#define NCHUNK 28
#define NPART (NMAPS*NCHUNK)

// ---------------- scratch ----------------
__device__ __align__(128) float g_X   [NB*NTOK*KVD];
__device__ __align__(128) float g_XT  [NB*KVD*NTOK];
__device__ __align__(128) float g_cx2 [NB*NTOK*CC2];
__device__ __align__(128) float g_c2T [NB*CC2*NTOK];
__device__ __align__(128) float g_Gt  [NB*KVD*CC2];
__device__ __align__(128) float g_T   [NMAPS*CC2*KVD];
__device__ __align__(128) float g_S   [NMAPS*CC2*KVD];
__device__ __align__(128) float g_Mt  [NB*CC2*KVD];
__device__ __align__(128) float g_ctx [NB*NTOK*CC2];
__device__ __align__(128) float g_res [NB*NTOK*CC2];
__device__ __align__(128) float g_x2  [NB*NTOK*CC2];
__device__ __align__(128) float g_h1  [NB*NTOK*CC2*4];
__device__ __align__(128) float g_WqT [NH*CC2*CC2];
__device__ __align__(128) float g_WkT [NH*KVD*KVD];
__device__ __align__(128) float g_WoutT[CC2*CC2];
__device__ __align__(128) float g_fc1T[CC2*4*CC2];
__device__ __align__(128) float g_fc2T[CC2*CC2*4];
__device__ __align__(128) float g_part[NPART*2];
__device__ __align__(128) float g_stats[NMAPS*2];

// ---------------- helpers ----------------
__device__ __forceinline__ uint32_t smem_u32(const void* p) {
    uint32_t a;
    asm("{ .reg .u64 t; cvta.to.shared.u64 t, %1; cvt.u32.u64 %0, t; }" : "=r"(a) : "l"(p));
    return a;
}
#define CP_ASYNC16(sa, ga) \
    asm volatile("cp.async.cg.shared.global [%0], [%1], 16;" :: "r"(sa), "l"(ga) : "memory")
#define CP_COMMIT() asm volatile("cp.async.commit_group;" ::: "memory")
#define CP_WAIT1()  asm volatile("cp.async.wait_group 1;" ::: "memory")
#define CP_WAIT0()  asm volatile("cp.async.wait_group 0;" ::: "memory")

__device__ __forceinline__ void mma_tf32(float* c, const uint32_t* a, const uint32_t* b) {
    asm volatile(
        "mma.sync.aligned.m16n8k8.row.col.f32.tf32.tf32.f32 "
        "{%0,%1,%2,%3}, {%4,%5,%6,%7}, {%8,%9}, {%0,%1,%2,%3};"
        : "+f"(c[0]), "+f"(c[1]), "+f"(c[2]), "+f"(c[3])
        : "r"(a[0]), "r"(a[1]), "r"(a[2]), "r"(a[3]), "r"(b[0]), "r"(b[1]));
}

// ---------------- tensor-core GEMM: D[M,N] = alpha * sum_seg A[M,K] @ B[N,K]^T
#define BM 128
#define BN 128
#define BK 32
#define PAD 36
#define SM_BUF (128*PAD)            // floats per operand buffer
#define SM_TOTAL (4*SM_BUF*4)       // bytes: A0 A1 B0 B1

struct TCP {
    const float *A, *B; float *C;
    int lda, ldb, ldc, K;
    long sA, sB, sC;
    int aSel, bSel, nseg;
    long segA, segB;
    float alpha;
    const float* bias;
    const float* add; int ldAdd; long sAdd;
};

// EPI: 0 plain; 1 bias+gelu; 2 (+bias)+add
template <int EPI>
__global__ void __launch_bounds__(256) gemm_mma(TCP p)
{
    extern __shared__ float sm[];
    float* Asm = sm;              // [2][128][PAD]
    float* Bsm = sm + 2 * SM_BUF;
    uint32_t sbA = smem_u32(Asm), sbB = smem_u32(Bsm);

    int t = threadIdx.x, lane = t & 31, w = t >> 5;
    int z = blockIdx.z;
    int m0 = blockIdx.y * BM, n0 = blockIdx.x * BN;
    int az = p.aSel == 0 ? z : (p.aSel == 1 ? (z & 3) : (z >> 2));
    int bz = p.bSel == 0 ? z : (p.bSel == 1 ? (z & 3) : (z >> 2));
    const float* Ab = p.A + (long)az * p.sA + (size_t)m0 * p.lda;
    const float* Bb = p.B + (long)bz * p.sB + (size_t)n0 * p.ldb;
    float* Cz = p.C + (long)z * p.sC;

    int kIters = p.K >> 5;
    int nIt = kIters * p.nseg;

    int lrow = t >> 1;                 // 0..127
    int lq = (t & 1) << 2;             // 0 or 4 (two 16B chunks per thread per pass... )
    // 128 rows x 8 chunks = 1024 tasks / 256 threads = 4 tasks each.
    // task layout: row = task>>3, q = task&7
    int seg = 0, kk = 0;
    (void)lrow; (void)lq;

    // prologue loads (buf 0)
    {
        const float* Ag = Ab; const float* Bg = Bb;
        #pragma unroll
        for (int i = 0; i < 4; i++) {
            int task = t + i * 256, row = task >> 3, q = task & 7;
            CP_ASYNC16(sbA + (row * PAD + q * 4) * 4, Ag + (size_t)row * p.lda + q * 4);
            CP_ASYNC16(sbB + (row * PAD + q * 4) * 4, Bg + (size_t)row * p.ldb + q * 4);
        }
        CP_COMMIT();
    }
    kk += 32; if (kk == p.K) { kk = 0; seg++; }

    int wm = (w >> 2) * 64, wn = (w & 3) * 32;
    float acc[4][4][4] = {};

    for (int it = 0; it < nIt; it++) {
        int buf = it & 1;
        if (it + 1 < nIt) {
            int nb = buf ^ 1;
            const float* Ag = Ab + (long)seg * p.segA + kk;
            const float* Bg = Bb + (long)seg * p.segB + kk;
            uint32_t da = sbA + nb * SM_BUF * 4, db = sbB + nb * SM_BUF * 4;
            #pragma unroll
            for (int i = 0; i < 4; i++) {
                int task = t + i * 256, row = task >> 3, q = task & 7;
                CP_ASYNC16(da + (row * PAD + q * 4) * 4, Ag + (size_t)row * p.lda + q * 4);
                CP_ASYNC16(db + (row * PAD + q * 4) * 4, Bg + (size_t)row * p.ldb + q * 4);
            }
            CP_COMMIT();
            kk += 32; if (kk == p.K) { kk = 0; seg++; }
            CP_WAIT1();
        } else {
            CP_WAIT0();
        }
        __syncthreads();

        const uint32_t* Ai = (const uint32_t*)(Asm + buf * SM_BUF);
        const uint32_t* Bi = (const uint32_t*)(Bsm + buf * SM_BUF);
        int arow = wm + (lane >> 2), brow = wn + (lane >> 2);
        #pragma unroll
        for (int ks = 0; ks < 4; ks++) {
            int ac = ks * 8 + (lane & 3);
            uint32_t a[4][4], b[4][2];
            #pragma unroll
            for (int mi = 0; mi < 4; mi++) {
                const uint32_t* p0 = Ai + (size_t)(arow + mi * 16) * PAD + ac;
                a[mi][0] = p0[0];
                a[mi][2] = p0[4];
                a[mi][1] = p0[8 * PAD];
                a[mi][3] = p0[8 * PAD + 4];
            }
            #pragma unroll
            for (int ni = 0; ni < 4; ni++) {
                const uint32_t* p0 = Bi + (size_t)(brow + ni * 8) * PAD + ac;
                b[ni][0] = p0[0];
                b[ni][1] = p0[4];
            }
            #pragma unroll
            for (int mi = 0; mi < 4; mi++)
                #pragma unroll
                for (int ni = 0; ni < 4; ni++)
                    mma_tf32(acc[mi][ni], a[mi], b[ni]);
        }
        __syncthreads();
    }

    // -------- epilogue: direct stores --------
    #pragma unroll
    for (int mi = 0; mi < 4; mi++) {
        #pragma unroll
        for (int ni = 0; ni < 4; ni++) {
            int r0 = m0 + wm + mi * 16 + (lane >> 2);
            int cc = n0 + wn + ni * 8 + (lane & 3) * 2;
            #pragma unroll
            for (int h = 0; h < 2; h++) {
                int gr = r0 + h * 8;
                float v0 = p.alpha * acc[mi][ni][h * 2 + 0];
                float v1 = p.alpha * acc[mi][ni][h * 2 + 1];
                if (EPI == 1) {
                    v0 += p.bias[cc]; v1 += p.bias[cc + 1];
                    v0 = 0.5f * v0 * (1.f + erff(v0 * 0.70710678118654752f));
                    v1 = 0.5f * v1 * (1.f + erff(v1 * 0.70710678118654752f));
                }
                if (EPI == 2) {
                    if (p.bias) { v0 += p.bias[cc]; v1 += p.bias[cc + 1]; }
                    const float* ap = p.add + (long)z * p.sAdd + (size_t)gr * p.ldAdd + cc;
                    float2 av = *(const float2*)ap;
                    v0 += av.x; v1 += av.y;
                }
                *(float2*)&Cz[(size_t)gr * p.ldc + cc] = make_float2(v0, v1);
            }
        }
    }
}

// ---------------- transpose ----------------
__global__ void __launch_bounds__(256) transpose_kernel(
    const float* __restrict__ in, float* __restrict__ out, int rows, int cols)
{
    __shared__ float tile[32][33];
    long zo = (long)blockIdx.z * rows * cols;
    const float* ip = in + zo;
    float* op = out + zo;
    int c0 = blockIdx.x * 32, r0 = blockIdx.y * 32;
    int tx = threadIdx.x & 31, ty = threadIdx.x >> 5;
    #pragma unroll
    for (int i = 0; i < 4; i++)
        tile[ty + i * 8][tx] = ip[(size_t)(r0 + ty + i * 8) * cols + c0 + tx];
    __syncthreads();
    #pragma unroll
    for (int i = 0; i < 4; i++)
        op[(size_t)(c0 + ty + i * 8) * rows + r0 + tx] = tile[tx][ty + i * 8];
}

// ---------------- elementwise ----------------
__device__ __forceinline__ float blockReduceSum(float v, float* sbuf) {
    #pragma unroll
    for (int o = 16; o > 0; o >>= 1) v += __shfl_down_sync(0xffffffffu, v, o);
    int lane = threadIdx.x & 31, w = threadIdx.x >> 5;
    if (lane == 0) sbuf[w] = v;
    __syncthreads();
    float tot = 0.f;
    #pragma unroll
    for (int i = 0; i < 8; i++) tot += sbuf[i];
    __syncthreads();
    return tot;
}

__global__ void __launch_bounds__(256) ln_all_kernel(
    const float* __restrict__ e1, const float* __restrict__ e2, const float* __restrict__ e3,
    const float* __restrict__ g1, const float* __restrict__ b1,
    const float* __restrict__ ga, const float* __restrict__ ba,
    float* __restrict__ X, float* __restrict__ cx2)
{
    __shared__ float xs[KVD];
    __shared__ float red[8];
    int tok = blockIdx.x, t = threadIdx.x;
    const float* p1 = e1 + (size_t)tok * 256;
    const float* p2 = e2 + (size_t)tok * 512;
    const float* p3 = e3 + (size_t)tok * 1024;
    xs[t] = p1[t];
    xs[256 + t] = p2[t];
    xs[512 + t] = p2[256 + t];
    #pragma unroll
    for (int i = 0; i < 4; i++) xs[768 + t + i * 256] = p3[t + i * 256];
    __syncthreads();
    float s = 0.f, ss = 0.f, s2 = 0.f, ss2 = 0.f;
    for (int i = t; i < KVD; i += 256) { float x = xs[i]; s += x; ss += x * x; }
    for (int i = t; i < 512; i += 256) { float x = xs[256 + i]; s2 += x; ss2 += x * x; }
    s  = blockReduceSum(s,  red);
    ss = blockReduceSum(ss, red);
    s2 = blockReduceSum(s2, red);
    ss2= blockReduceSum(ss2,red);
    float m  = s * (1.f / KVD), r = rsqrtf(ss * (1.f / KVD) - m * m + 1e-6f);
    float m2 = s2 * (1.f / 512.f), r2 = rsqrtf(ss2 * (1.f / 512.f) - m2 * m2 + 1e-6f);
    float* Xo = X + (size_t)tok * KVD;
    float* co = cx2 + (size_t)tok * 512;
    for (int i = t; i < KVD; i += 256) Xo[i] = (xs[i] - m) * r * ga[i] + ba[i];
    for (int i = t; i < 512; i += 256) co[i] = (xs[256 + i] - m2) * r2 * g1[i] + b1[i];
}

__global__ void __launch_bounds__(256) ln512_kernel(
    const float* __restrict__ in, const float* __restrict__ g, const float* __restrict__ b,
    float* __restrict__ out)
{
    __shared__ float red[8];
    int tok = blockIdx.x, t = threadIdx.x;
    const float* p = in + (size_t)tok * 512;
    float x0 = p[t], x1 = p[t + 256];
    float s = blockReduceSum(x0 + x1, red);
    float ss = blockReduceSum(x0 * x0 + x1 * x1, red);
    float m = s * (1.f / 512.f);
    float r = rsqrtf(ss * (1.f / 512.f) - m * m + 1e-6f);
    float* o = out + (size_t)tok * 512;
    o[t] = (x0 - m) * r * g[t] + b[t];
    o[t + 256] = (x1 - m) * r * g[t + 256] + b[t + 256];
}

__global__ void __launch_bounds__(256) stats_part_kernel(const float* __restrict__ S,
                                                         float* __restrict__ part)
{
    __shared__ float red[8];
    int bx = blockIdx.x, t = threadIdx.x;
    const float4* p = (const float4*)(S + (size_t)bx * 32768);
    float s = 0.f, ss = 0.f;
    for (int i = t; i < 8192; i += 256) {
        float4 v = p[i];
        s  += v.x + v.y + v.z + v.w;
        ss += v.x * v.x + v.y * v.y + v.z * v.z + v.w * v.w;
    }
    s = blockReduceSum(s, red);
    ss = blockReduceSum(ss, red);
    if (t == 0) { part[bx * 2] = s; part[bx * 2 + 1] = ss; }
}

__global__ void stats_final_kernel(const float* __restrict__ part, float* __restrict__ stats)
{
    int m = threadIdx.x;
    if (m < NMAPS) {
        float s = 0.f, ss = 0.f;
        for (int c = 0; c < NCHUNK; c++) {
            s  += part[(m * NCHUNK + c) * 2];
            ss += part[(m * NCHUNK + c) * 2 + 1];
        }
        float inv = 1.f / (float)MAPELEMS;
        float mean = s * inv;
        float var = ss * inv - mean * mean;
        stats[2 * m] = mean;
        stats[2 * m + 1] = rsqrtf(var + 1e-5f);
    }
}

__global__ void __launch_bounds__(256) softmax_kernel(float* __restrict__ S,
                                                      const float* __restrict__ stats)
{
    __shared__ float red[8];
    int row = blockIdx.x, t = threadIdx.x;
    int map = row >> 9;
    float r = stats[map * 2 + 1];
    float* p = S + (size_t)row * KVD;
    float v[7];
    float mx = -1e30f;
    #pragma unroll
    for (int j = 0; j < 7; j++) { v[j] = p[t + j * 256] * r; mx = fmaxf(mx, v[j]); }
    #pragma unroll
    for (int o = 16; o > 0; o >>= 1) mx = fmaxf(mx, __shfl_xor_sync(0xffffffffu, mx, o));
    int lane = t & 31, w = t >> 5;
    if (lane == 0) red[w] = mx;
    __syncthreads();
    float bm = red[0];
    #pragma unroll
    for (int i = 1; i < 8; i++) bm = fmaxf(bm, red[i]);
    __syncthreads();
    float s = 0.f;
    #pragma unroll
    for (int j = 0; j < 7; j++) { v[j] = expf(v[j] - bm); s += v[j]; }
    s = blockReduceSum(s, red);
    float inv = 1.f / s;
    #pragma unroll
    for (int j = 0; j < 7; j++) p[t + j * 256] = v[j] * inv;
}

// ---------------- host ----------------
static inline TCP mkP(const float* A, const float* B, float* C,
                      int lda, int ldb, int ldc, int K,
                      long sA, long sB, long sC, int aSel, int bSel,
                      int nseg, long segA, long segB, float alpha,
                      const float* bias, const float* add, int ldAdd, long sAdd)
{
    TCP p; p.A = A; p.B = B; p.C = C; p.lda = lda; p.ldb = ldb; p.ldc = ldc; p.K = K;
    p.sA = sA; p.sB = sB; p.sC = sC; p.aSel = aSel; p.bSel = bSel;
    p.nseg = nseg; p.segA = segA; p.segB = segB; p.alpha = alpha;
    p.bias = bias; p.add = add; p.ldAdd = ldAdd; p.sAdd = sAdd;
    return p;
}

extern "C" void kernel_launch(void* const* d_in, const int* in_sizes, int n_in,
                              void* d_out, int out_size)
{
    const float* emb1   = (const float*)d_in[0];
    const float* emb2   = (const float*)d_in[1];
    const float* emb3   = (const float*)d_in[2];
    const float* Wq     = (const float*)d_in[3];
    const float* Wk     = (const float*)d_in[4];
    const float* Wv     = (const float*)d_in[5];
    const float* Wout   = (const float*)d_in[6];
    const float* ln1_g  = (const float*)d_in[7];
    const float* ln1_b  = (const float*)d_in[8];
    const float* lnall_g= (const float*)d_in[9];
    const float* lnall_b= (const float*)d_in[10];
    const float* lnffn_g= (const float*)d_in[11];
    const float* lnffn_b= (const float*)d_in[12];
    const float* fc1_w  = (const float*)d_in[13];
    const float* fc1_b  = (const float*)d_in[14];
    const float* fc2_w  = (const float*)d_in[15];
    const float* fc2_b  = (const float*)d_in[16];
    float* out = (float*)d_out;

    cudaFuncSetAttribute(gemm_mma<0>, cudaFuncAttributeMaxDynamicSharedMemorySize, SM_TOTAL);
    cudaFuncSetAttribute(gemm_mma<1>, cudaFuncAttributeMaxDynamicSharedMemorySize, SM_TOTAL);
    cudaFuncSetAttribute(gemm_mma<2>, cudaFuncAttributeMaxDynamicSharedMemorySize, SM_TOTAL);

    float *X,*XT,*cx2,*c2T,*Gt,*T,*S,*Mt,*ctx,*res,*x2,*h1;
    float *WqT,*WkT,*WoutT,*fc1T,*fc2T,*part,*stats;
    cudaGetSymbolAddress((void**)&X,    g_X);
    cudaGetSymbolAddress((void**)&XT,   g_XT);
    cudaGetSymbolAddress((void**)&cx2,  g_cx2);
    cudaGetSymbolAddress((void**)&c2T,  g_c2T);
    cudaGetSymbolAddress((void**)&Gt,   g_Gt);
    cudaGetSymbolAddress((void**)&T,    g_T);
    cudaGetSymbolAddress((void**)&S,    g_S);
    cudaGetSymbolAddress((void**)&Mt,   g_Mt);
    cudaGetSymbolAddress((void**)&ctx,  g_ctx);
    cudaGetSymbolAddress((void**)&res,  g_res);
    cudaGetSymbolAddress((void**)&x2,   g_x2);
    cudaGetSymbolAddress((void**)&h1,   g_h1);
    cudaGetSymbolAddress((void**)&WqT,  g_WqT);
    cudaGetSymbolAddress((void**)&WkT,  g_WkT);
    cudaGetSymbolAddress((void**)&WoutT,g_WoutT);
    cudaGetSymbolAddress((void**)&fc1T, g_fc1T);
    cudaGetSymbolAddress((void**)&fc2T, g_fc2T);
    cudaGetSymbolAddress((void**)&part, g_part);
    cudaGetSymbolAddress((void**)&stats,g_stats);

    const long MAPSZ = (long)CC2 * KVD;
    const float inv_sqrt_kv = 1.f / sqrtf((float)KVD);

    // weight transposes
    transpose_kernel<<<dim3(16,16,4), 256>>>(Wq, WqT, 512, 512);
    transpose_kernel<<<dim3(56,56,4), 256>>>(Wk, WkT, KVD, KVD);
    transpose_kernel<<<dim3(16,16,1), 256>>>(Wout, WoutT, 512, 512);
    transpose_kernel<<<dim3(64,16,1), 256>>>(fc1_w, fc1T, 512, 2048);
    transpose_kernel<<<dim3(16,64,1), 256>>>(fc2_w, fc2T, 2048, 512);

    // 1. LayerNorms + activation transposes
    ln_all_kernel<<<NB*NTOK, 256>>>(emb1, emb2, emb3, ln1_g, ln1_b,
                                    lnall_g, lnall_b, X, cx2);
    transpose_kernel<<<dim3(56,32,8), 256>>>(X, XT, NTOK, KVD);
    transpose_kernel<<<dim3(16,32,8), 256>>>(cx2, c2T, NTOK, 512);

    // 2. Gt[b][j][c] = sum_t XT[j,t] c2T[c,t] : M=KVD, N=512, K=1024
    gemm_mma<0><<<dim3(4,14,8), 256, SM_TOTAL>>>(
        mkP(XT, c2T, Gt, NTOK, NTOK, 512, NTOK,
            (long)KVD*NTOK, (long)512*NTOK, (long)KVD*512, 0, 0,
            1, 0, 0, 1.f, nullptr, nullptr, 0, 0));

    // 3. T[z][d][j] = sum_c WqT[h][d,c] Gt[b][j,c] : M=512, N=KVD, K=512
    gemm_mma<0><<<dim3(14,4,32), 256, SM_TOTAL>>>(
        mkP(WqT, Gt, T, 512, 512, KVD, 512,
            (long)512*512, (long)KVD*512, MAPSZ, 1, 2,
            1, 0, 0, 1.f, nullptr, nullptr, 0, 0));

    // 4. S[z][d][k'] = (1/sqrt(KV)) sum_j T[d,j] WkT[h][k',j] : M=512, N=KVD, K=KVD
    gemm_mma<0><<<dim3(14,4,32), 256, SM_TOTAL>>>(
        mkP(T, WkT, S, KVD, KVD, KVD, KVD,
            MAPSZ, (long)KVD*KVD, MAPSZ, 0, 1,
            1, 0, 0, inv_sqrt_kv, nullptr, nullptr, 0, 0));

    // 5-6. IN stats + softmax (mean cancels; rstd only)
    stats_part_kernel<<<NPART, 256>>>(S, part);
    stats_final_kernel<<<1, 32>>>(part, stats);
    softmax_kernel<<<NMAPS*512, 256>>>(S, stats);

    // 7. Mt[b][c][j] = (1/H) sum_h sum_k probs[b,h][c,k] Wv[h][j,k] : M=512, N=KVD, 4 segs
    gemm_mma<0><<<dim3(14,4,8), 256, SM_TOTAL>>>(
        mkP(S, Wv, Mt, KVD, KVD, KVD, KVD,
            4*MAPSZ, 0, (long)512*KVD, 0, 0,
            4, MAPSZ, (long)KVD*KVD, 0.25f, nullptr, nullptr, 0, 0));

    // 8. ctx[b][t][c] = sum_j X[t,j] Mt[c,j] : M=1024, N=512, K=KVD
    gemm_mma<0><<<dim3(4,8,8), 256, SM_TOTAL>>>(
        mkP(X, Mt, ctx, KVD, KVD, 512, KVD,
            (long)NTOK*KVD, (long)512*KVD, (long)NTOK*512, 0, 0,
            1, 0, 0, 1.f, nullptr, nullptr, 0, 0));

    // 9. res = ctx @ Wout + emb2 : M=8192, N=512, K=512
    gemm_mma<2><<<dim3(4,64,1), 256, SM_TOTAL>>>(
        mkP(ctx, WoutT, res, 512, 512, 512, 512,
            0, 0, 0, 0, 0, 1, 0, 0, 1.f, nullptr, emb2, 512, 0));

    // 10. x2 = LN(res)
    ln512_kernel<<<NB*NTOK, 256>>>(res, lnffn_g, lnffn_b, x2);

    // 11. h1 = gelu(x2 @ fc1 + b1) : M=8192, N=2048, K=512
    gemm_mma<1><<<dim3(16,64,1), 256, SM_TOTAL>>>(
        mkP(x2, fc1T, h1, 512, 512, 2048, 512,
            0, 0, 0, 0, 0, 1, 0, 0, 1.f, fc1_b, nullptr, 0, 0));

    // 12. out = h1 @ fc2 + b2 + res : M=8192, N=512, K=2048
    gemm_mma<2><<<dim3(4,64,1), 256, SM_TOTAL>>>(
        mkP(h1, fc2T, out, 2048, 2048, 512, 2048,
            0, 0, 0, 0, 0, 1, 0, 0, 1.f, fc2_b, res, 512, 0));
}

// round 6
// speedup vs baseline: 4.1183x; 1.0029x over previous
#include <cuda_runtime.h>
#include <math.h>
#include <stdint.h>

#define NB 8
#define NTOK 1024
#define CC2 512
#define KVD 1792
#define NH 4
#define NMAPS (NB*NH)          // 32
#define MAPELEMS (CC2*KVD)     // 917504
#define NPART (NMAPS*56)       // 56 tiles per map (14 x 4)

// ---------------- scratch ----------------
__device__ __align__(128) float g_X   [NB*NTOK*KVD];
__device__ __align__(128) float g_XT  [NB*KVD*NTOK];
__device__ __align__(128) float g_cx2 [NB*NTOK*CC2];
__device__ __align__(128) float g_c2T [NB*CC2*NTOK];
__device__ __align__(128) float g_Gt  [NB*KVD*CC2];
__device__ __align__(128) float g_T   [NMAPS*CC2*KVD];
__device__ __align__(128) float g_S   [NMAPS*CC2*KVD];
__device__ __align__(128) float g_Mt  [NB*CC2*KVD];
__device__ __align__(128) float g_ctx [NB*NTOK*CC2];
__device__ __align__(128) float g_res [NB*NTOK*CC2];
__device__ __align__(128) float g_x2  [NB*NTOK*CC2];
__device__ __align__(128) float g_h1  [NB*NTOK*CC2*4];
__device__ __align__(128) float g_WqT [NH*CC2*CC2];
__device__ __align__(128) float g_WkT [NH*KVD*KVD];
__device__ __align__(128) float g_WoutT[CC2*CC2];
__device__ __align__(128) float g_fc1T[CC2*4*CC2];
__device__ __align__(128) float g_fc2T[CC2*CC2*4];
__device__ __align__(128) float g_part[NPART*2];

// ---------------- helpers ----------------
__device__ __forceinline__ uint32_t smem_u32(const void* p) {
    uint32_t a;
    asm("{ .reg .u64 t; cvta.to.shared.u64 t, %1; cvt.u32.u64 %0, t; }" : "=r"(a) : "l"(p));
    return a;
}
#define CP_ASYNC16(sa, ga) \
    asm volatile("cp.async.cg.shared.global [%0], [%1], 16;" :: "r"(sa), "l"(ga) : "memory")
#define CP_COMMIT() asm volatile("cp.async.commit_group;" ::: "memory")
#define CP_WAIT2()  asm volatile("cp.async.wait_group 2;" ::: "memory")

__device__ __forceinline__ void mma_tf32(float* c, const uint32_t* a, const uint32_t* b) {
    asm volatile(
        "mma.sync.aligned.m16n8k8.row.col.f32.tf32.tf32.f32 "
        "{%0,%1,%2,%3}, {%4,%5,%6,%7}, {%8,%9}, {%0,%1,%2,%3};"
        : "+f"(c[0]), "+f"(c[1]), "+f"(c[2]), "+f"(c[3])
        : "r"(a[0]), "r"(a[1]), "r"(a[2]), "r"(a[3]), "r"(b[0]), "r"(b[1]));
}

// ---------------- tensor-core GEMM: D[M,N] = alpha * sum_seg A[M,K] @ B[N,K]^T
#define BM 128
#define BN 128
#define PAD 36
#define SM_BUF (128*PAD)            // floats per operand buffer
#define NSTAGE 3
#define SM_TOTAL (NSTAGE*2*SM_BUF*4)  // 110592 bytes

struct TCP {
    const float *A, *B; float *C;
    int lda, ldb, ldc, K;
    long sA, sB, sC;
    int aSel, bSel, nseg;
    long segA, segB;
    float alpha;
    const float* bias;
    const float* add; int ldAdd; long sAdd;
    float* part;                // EPI 3: partial stats output
};

// EPI: 0 plain; 1 bias+gelu; 2 (+bias)+add; 3 plain + per-CTA IN partial stats
template <int EPI>
__global__ void __launch_bounds__(256, 2) gemm_mma(TCP p)
{
    extern __shared__ float sm[];
    uint32_t sb = smem_u32(sm);

    int t = threadIdx.x, lane = t & 31, w = t >> 5;
    int z = blockIdx.z;
    int m0 = blockIdx.y * BM, n0 = blockIdx.x * BN;
    int az = p.aSel == 0 ? z : (p.aSel == 1 ? (z & 3) : (z >> 2));
    int bz = p.bSel == 0 ? z : (p.bSel == 1 ? (z & 3) : (z >> 2));
    const float* Ab = p.A + (long)az * p.sA + (size_t)m0 * p.lda;
    const float* Bb = p.B + (long)bz * p.sB + (size_t)n0 * p.ldb;
    float* Cz = p.C + (long)z * p.sC;

    int kIters = p.K >> 5;
    int nIt = kIters * p.nseg;
    int seg = 0, kk = 0;

    // issue loads for a stage; buf in [0, NSTAGE)
    auto issue = [&](int buf) {
        const float* Ag = Ab + (long)seg * p.segA + kk;
        const float* Bg = Bb + (long)seg * p.segB + kk;
        uint32_t da = sb + (2 * buf) * SM_BUF * 4;
        uint32_t db = sb + (2 * buf + 1) * SM_BUF * 4;
        #pragma unroll
        for (int i = 0; i < 4; i++) {
            int task = t + i * 256, row = task >> 3, q = task & 7;
            CP_ASYNC16(da + (row * PAD + q * 4) * 4, Ag + (size_t)row * p.lda + q * 4);
            CP_ASYNC16(db + (row * PAD + q * 4) * 4, Bg + (size_t)row * p.ldb + q * 4);
        }
        CP_COMMIT();
        kk += 32; if (kk == p.K) { kk = 0; seg++; }
    };

    issue(0);
    if (nIt > 1) issue(1);

    int wm = (w >> 2) * 64, wn = (w & 3) * 32;
    float acc[4][4][4] = {};
    int arowL = wm + (lane >> 2), browL = wn + (lane >> 2);

    for (int it = 0; it < nIt; it++) {
        int buf = it % NSTAGE;
        if (it + 2 < nIt) issue((it + 2) % NSTAGE);
        else CP_COMMIT();                 // empty group keeps wait accounting uniform
        CP_WAIT2();
        __syncthreads();

        const uint32_t* Ai = (const uint32_t*)(sm + (2 * buf) * SM_BUF);
        const uint32_t* Bi = (const uint32_t*)(sm + (2 * buf + 1) * SM_BUF);
        #pragma unroll
        for (int ks = 0; ks < 4; ks++) {
            int ac = ks * 8 + (lane & 3);
            uint32_t a[4][4], b[4][2];
            #pragma unroll
            for (int mi = 0; mi < 4; mi++) {
                const uint32_t* p0 = Ai + (size_t)(arowL + mi * 16) * PAD + ac;
                a[mi][0] = p0[0];
                a[mi][2] = p0[4];
                a[mi][1] = p0[8 * PAD];
                a[mi][3] = p0[8 * PAD + 4];
            }
            #pragma unroll
            for (int ni = 0; ni < 4; ni++) {
                const uint32_t* p0 = Bi + (size_t)(browL + ni * 8) * PAD + ac;
                b[ni][0] = p0[0];
                b[ni][1] = p0[4];
            }
            #pragma unroll
            for (int mi = 0; mi < 4; mi++)
                #pragma unroll
                for (int ni = 0; ni < 4; ni++)
                    mma_tf32(acc[mi][ni], a[mi], b[ni]);
        }
        __syncthreads();
    }

    // -------- epilogue --------
    float psum = 0.f, psq = 0.f;
    #pragma unroll
    for (int mi = 0; mi < 4; mi++) {
        #pragma unroll
        for (int ni = 0; ni < 4; ni++) {
            int r0 = m0 + wm + mi * 16 + (lane >> 2);
            int cc = n0 + wn + ni * 8 + (lane & 3) * 2;
            #pragma unroll
            for (int h = 0; h < 2; h++) {
                int gr = r0 + h * 8;
                float v0 = p.alpha * acc[mi][ni][h * 2 + 0];
                float v1 = p.alpha * acc[mi][ni][h * 2 + 1];
                if (EPI == 1) {
                    v0 += p.bias[cc]; v1 += p.bias[cc + 1];
                    v0 = 0.5f * v0 * (1.f + erff(v0 * 0.70710678118654752f));
                    v1 = 0.5f * v1 * (1.f + erff(v1 * 0.70710678118654752f));
                }
                if (EPI == 2) {
                    if (p.bias) { v0 += p.bias[cc]; v1 += p.bias[cc + 1]; }
                    const float* ap = p.add + (long)z * p.sAdd + (size_t)gr * p.ldAdd + cc;
                    float2 av = *(const float2*)ap;
                    v0 += av.x; v1 += av.y;
                }
                if (EPI == 3) { psum += v0 + v1; psq += v0 * v0 + v1 * v1; }
                *(float2*)&Cz[(size_t)gr * p.ldc + cc] = make_float2(v0, v1);
            }
        }
    }
    if (EPI == 3) {
        // deterministic block reduce of (psum, psq) into part slot
        #pragma unroll
        for (int o = 16; o > 0; o >>= 1) {
            psum += __shfl_down_sync(0xffffffffu, psum, o);
            psq  += __shfl_down_sync(0xffffffffu, psq,  o);
        }
        if (lane == 0) { sm[w] = psum; sm[8 + w] = psq; }
        __syncthreads();
        if (t == 0) {
            float s = 0.f, ss = 0.f;
            #pragma unroll
            for (int i = 0; i < 8; i++) { s += sm[i]; ss += sm[8 + i]; }
            int idx = (z * 4 + blockIdx.y) * 14 + blockIdx.x;
            p.part[idx * 2] = s;
            p.part[idx * 2 + 1] = ss;
        }
    }
}

// ---------------- transpose ----------------
__global__ void __launch_bounds__(256) transpose_kernel(
    const float* __restrict__ in, float* __restrict__ out, int rows, int cols)
{
    __shared__ float tile[32][33];
    long zo = (long)blockIdx.z * rows * cols;
    const float* ip = in + zo;
    float* op = out + zo;
    int c0 = blockIdx.x * 32, r0 = blockIdx.y * 32;
    int tx = threadIdx.x & 31, ty = threadIdx.x >> 5;
    #pragma unroll
    for (int i = 0; i < 4; i++)
        tile[ty + i * 8][tx] = ip[(size_t)(r0 + ty + i * 8) * cols + c0 + tx];
    __syncthreads();
    #pragma unroll
    for (int i = 0; i < 4; i++)
        op[(size_t)(c0 + ty + i * 8) * rows + r0 + tx] = tile[tx][ty + i * 8];
}

// ---------------- elementwise ----------------
__device__ __forceinline__ float blockReduceSum(float v, float* sbuf) {
    #pragma unroll
    for (int o = 16; o > 0; o >>= 1) v += __shfl_down_sync(0xffffffffu, v, o);
    int lane = threadIdx.x & 31, w = threadIdx.x >> 5;
    if (lane == 0) sbuf[w] = v;
    __syncthreads();
    float tot = 0.f;
    #pragma unroll
    for (int i = 0; i < 8; i++) tot += sbuf[i];
    __syncthreads();
    return tot;
}

__global__ void __launch_bounds__(256) ln_all_kernel(
    const float* __restrict__ e1, const float* __restrict__ e2, const float* __restrict__ e3,
    const float* __restrict__ g1, const float* __restrict__ b1,
    const float* __restrict__ ga, const float* __restrict__ ba,
    float* __restrict__ X, float* __restrict__ cx2)
{
    __shared__ float xs[KVD];
    __shared__ float red[8];
    int tok = blockIdx.x, t = threadIdx.x;
    const float* p1 = e1 + (size_t)tok * 256;
    const float* p2 = e2 + (size_t)tok * 512;
    const float* p3 = e3 + (size_t)tok * 1024;
    xs[t] = p1[t];
    xs[256 + t] = p2[t];
    xs[512 + t] = p2[256 + t];
    #pragma unroll
    for (int i = 0; i < 4; i++) xs[768 + t + i * 256] = p3[t + i * 256];
    __syncthreads();
    float s = 0.f, ss = 0.f, s2 = 0.f, ss2 = 0.f;
    for (int i = t; i < KVD; i += 256) { float x = xs[i]; s += x; ss += x * x; }
    for (int i = t; i < 512; i += 256) { float x = xs[256 + i]; s2 += x; ss2 += x * x; }
    s  = blockReduceSum(s,  red);
    ss = blockReduceSum(ss, red);
    s2 = blockReduceSum(s2, red);
    ss2= blockReduceSum(ss2,red);
    float m  = s * (1.f / KVD), r = rsqrtf(ss * (1.f / KVD) - m * m + 1e-6f);
    float m2 = s2 * (1.f / 512.f), r2 = rsqrtf(ss2 * (1.f / 512.f) - m2 * m2 + 1e-6f);
    float* Xo = X + (size_t)tok * KVD;
    float* co = cx2 + (size_t)tok * 512;
    for (int i = t; i < KVD; i += 256) Xo[i] = (xs[i] - m) * r * ga[i] + ba[i];
    for (int i = t; i < 512; i += 256) co[i] = (xs[256 + i] - m2) * r2 * g1[i] + b1[i];
}

__global__ void __launch_bounds__(256) ln512_kernel(
    const float* __restrict__ in, const float* __restrict__ g, const float* __restrict__ b,
    float* __restrict__ out)
{
    __shared__ float red[8];
    int tok = blockIdx.x, t = threadIdx.x;
    const float* p = in + (size_t)tok * 512;
    float x0 = p[t], x1 = p[t + 256];
    float s = blockReduceSum(x0 + x1, red);
    float ss = blockReduceSum(x0 * x0 + x1 * x1, red);
    float m = s * (1.f / 512.f);
    float r = rsqrtf(ss * (1.f / 512.f) - m * m + 1e-6f);
    float* o = out + (size_t)tok * 512;
    o[t] = (x0 - m) * r * g[t] + b[t];
    o[t + 256] = (x1 - m) * r * g[t + 256] + b[t + 256];
}

// softmax over KV; computes rstd from the 56 GEMM-tile partials per map
__global__ void __launch_bounds__(256) softmax_kernel(float* __restrict__ S,
                                                      const float* __restrict__ part)
{
    __shared__ float red[8];
    int row = blockIdx.x, t = threadIdx.x;
    int map = row >> 9;
    // reduce 56 partial (sum, sumsq) pairs — deterministic, redundant per block
    float s0 = 0.f, q0 = 0.f;
    const float2* pp = (const float2*)part + map * 56;
    #pragma unroll 8
    for (int i = 0; i < 56; i++) { float2 v = pp[i]; s0 += v.x; q0 += v.y; }
    float invn = 1.f / (float)MAPELEMS;
    float mean = s0 * invn;
    float r = rsqrtf(q0 * invn - mean * mean + 1e-5f);

    float* p = S + (size_t)row * KVD;
    float v[7];
    float mx = -1e30f;
    #pragma unroll
    for (int j = 0; j < 7; j++) { v[j] = p[t + j * 256] * r; mx = fmaxf(mx, v[j]); }
    #pragma unroll
    for (int o = 16; o > 0; o >>= 1) mx = fmaxf(mx, __shfl_xor_sync(0xffffffffu, mx, o));
    int lane = t & 31, w = t >> 5;
    if (lane == 0) red[w] = mx;
    __syncthreads();
    float bm = red[0];
    #pragma unroll
    for (int i = 1; i < 8; i++) bm = fmaxf(bm, red[i]);
    __syncthreads();
    float s = 0.f;
    #pragma unroll
    for (int j = 0; j < 7; j++) { v[j] = expf(v[j] - bm); s += v[j]; }
    s = blockReduceSum(s, red);
    float inv = 1.f / s;
    #pragma unroll
    for (int j = 0; j < 7; j++) p[t + j * 256] = v[j] * inv;
}

// ---------------- host ----------------
static inline TCP mkP(const float* A, const float* B, float* C,
                      int lda, int ldb, int ldc, int K,
                      long sA, long sB, long sC, int aSel, int bSel,
                      int nseg, long segA, long segB, float alpha,
                      const float* bias, const float* add, int ldAdd, long sAdd,
                      float* part = nullptr)
{
    TCP p; p.A = A; p.B = B; p.C = C; p.lda = lda; p.ldb = ldb; p.ldc = ldc; p.K = K;
    p.sA = sA; p.sB = sB; p.sC = sC; p.aSel = aSel; p.bSel = bSel;
    p.nseg = nseg; p.segA = segA; p.segB = segB; p.alpha = alpha;
    p.bias = bias; p.add = add; p.ldAdd = ldAdd; p.sAdd = sAdd; p.part = part;
    return p;
}

extern "C" void kernel_launch(void* const* d_in, const int* in_sizes, int n_in,
                              void* d_out, int out_size)
{
    const float* emb1   = (const float*)d_in[0];
    const float* emb2   = (const float*)d_in[1];
    const float* emb3   = (const float*)d_in[2];
    const float* Wq     = (const float*)d_in[3];
    const float* Wk     = (const float*)d_in[4];
    const float* Wv     = (const float*)d_in[5];
    const float* Wout   = (const float*)d_in[6];
    const float* ln1_g  = (const float*)d_in[7];
    const float* ln1_b  = (const float*)d_in[8];
    const float* lnall_g= (const float*)d_in[9];
    const float* lnall_b= (const float*)d_in[10];
    const float* lnffn_g= (const float*)d_in[11];
    const float* lnffn_b= (const float*)d_in[12];
    const float* fc1_w  = (const float*)d_in[13];
    const float* fc1_b  = (const float*)d_in[14];
    const float* fc2_w  = (const float*)d_in[15];
    const float* fc2_b  = (const float*)d_in[16];
    float* out = (float*)d_out;

    cudaFuncSetAttribute(gemm_mma<0>, cudaFuncAttributeMaxDynamicSharedMemorySize, SM_TOTAL);
    cudaFuncSetAttribute(gemm_mma<1>, cudaFuncAttributeMaxDynamicSharedMemorySize, SM_TOTAL);
    cudaFuncSetAttribute(gemm_mma<2>, cudaFuncAttributeMaxDynamicSharedMemorySize, SM_TOTAL);
    cudaFuncSetAttribute(gemm_mma<3>, cudaFuncAttributeMaxDynamicSharedMemorySize, SM_TOTAL);

    float *X,*XT,*cx2,*c2T,*Gt,*T,*S,*Mt,*ctx,*res,*x2,*h1;
    float *WqT,*WkT,*WoutT,*fc1T,*fc2T,*part;
    cudaGetSymbolAddress((void**)&X,    g_X);
    cudaGetSymbolAddress((void**)&XT,   g_XT);
    cudaGetSymbolAddress((void**)&cx2,  g_cx2);
    cudaGetSymbolAddress((void**)&c2T,  g_c2T);
    cudaGetSymbolAddress((void**)&Gt,   g_Gt);
    cudaGetSymbolAddress((void**)&T,    g_T);
    cudaGetSymbolAddress((void**)&S,    g_S);
    cudaGetSymbolAddress((void**)&Mt,   g_Mt);
    cudaGetSymbolAddress((void**)&ctx,  g_ctx);
    cudaGetSymbolAddress((void**)&res,  g_res);
    cudaGetSymbolAddress((void**)&x2,   g_x2);
    cudaGetSymbolAddress((void**)&h1,   g_h1);
    cudaGetSymbolAddress((void**)&WqT,  g_WqT);
    cudaGetSymbolAddress((void**)&WkT,  g_WkT);
    cudaGetSymbolAddress((void**)&WoutT,g_WoutT);
    cudaGetSymbolAddress((void**)&fc1T, g_fc1T);
    cudaGetSymbolAddress((void**)&fc2T, g_fc2T);
    cudaGetSymbolAddress((void**)&part, g_part);

    const long MAPSZ = (long)CC2 * KVD;
    const float inv_sqrt_kv = 1.f / sqrtf((float)KVD);

    // weight transposes
    transpose_kernel<<<dim3(16,16,4), 256>>>(Wq, WqT, 512, 512);
    transpose_kernel<<<dim3(56,56,4), 256>>>(Wk, WkT, KVD, KVD);
    transpose_kernel<<<dim3(16,16,1), 256>>>(Wout, WoutT, 512, 512);
    transpose_kernel<<<dim3(64,16,1), 256>>>(fc1_w, fc1T, 512, 2048);
    transpose_kernel<<<dim3(16,64,1), 256>>>(fc2_w, fc2T, 2048, 512);

    // 1. LayerNorms + activation transposes
    ln_all_kernel<<<NB*NTOK, 256>>>(emb1, emb2, emb3, ln1_g, ln1_b,
                                    lnall_g, lnall_b, X, cx2);
    transpose_kernel<<<dim3(56,32,8), 256>>>(X, XT, NTOK, KVD);
    transpose_kernel<<<dim3(16,32,8), 256>>>(cx2, c2T, NTOK, 512);

    // 2. Gt[b][j][c] : M=KVD, N=512, K=1024
    gemm_mma<0><<<dim3(4,14,8), 256, SM_TOTAL>>>(
        mkP(XT, c2T, Gt, NTOK, NTOK, 512, NTOK,
            (long)KVD*NTOK, (long)512*NTOK, (long)KVD*512, 0, 0,
            1, 0, 0, 1.f, nullptr, nullptr, 0, 0));

    // 3. T[z][d][j] : M=512, N=KVD, K=512
    gemm_mma<0><<<dim3(14,4,32), 256, SM_TOTAL>>>(
        mkP(WqT, Gt, T, 512, 512, KVD, 512,
            (long)512*512, (long)KVD*512, MAPSZ, 1, 2,
            1, 0, 0, 1.f, nullptr, nullptr, 0, 0));

    // 4. S[z][d][k'] : M=512, N=KVD, K=KVD ; fused IN partial stats
    gemm_mma<3><<<dim3(14,4,32), 256, SM_TOTAL>>>(
        mkP(T, WkT, S, KVD, KVD, KVD, KVD,
            MAPSZ, (long)KVD*KVD, MAPSZ, 0, 1,
            1, 0, 0, inv_sqrt_kv, nullptr, nullptr, 0, 0, part));

    // 5. probs = softmax(rstd * S) — rstd folded in from partials
    softmax_kernel<<<NMAPS*512, 256>>>(S, part);

    // 6. Mt[b][c][j] : M=512, N=KVD, 4 segs over h
    gemm_mma<0><<<dim3(14,4,8), 256, SM_TOTAL>>>(
        mkP(S, Wv, Mt, KVD, KVD, KVD, KVD,
            4*MAPSZ, 0, (long)512*KVD, 0, 0,
            4, MAPSZ, (long)KVD*KVD, 0.25f, nullptr, nullptr, 0, 0));

    // 7. ctx[b][t][c] : M=1024, N=512, K=KVD
    gemm_mma<0><<<dim3(4,8,8), 256, SM_TOTAL>>>(
        mkP(X, Mt, ctx, KVD, KVD, 512, KVD,
            (long)NTOK*KVD, (long)512*KVD, (long)NTOK*512, 0, 0,
            1, 0, 0, 1.f, nullptr, nullptr, 0, 0));

    // 8. res = ctx @ Wout + emb2 : M=8192, N=512, K=512
    gemm_mma<2><<<dim3(4,64,1), 256, SM_TOTAL>>>(
        mkP(ctx, WoutT, res, 512, 512, 512, 512,
            0, 0, 0, 0, 0, 1, 0, 0, 1.f, nullptr, emb2, 512, 0));

    // 9. x2 = LN(res)
    ln512_kernel<<<NB*NTOK, 256>>>(res, lnffn_g, lnffn_b, x2);

    // 10. h1 = gelu(x2 @ fc1 + b1) : M=8192, N=2048, K=512
    gemm_mma<1><<<dim3(16,64,1), 256, SM_TOTAL>>>(
        mkP(x2, fc1T, h1, 512, 512, 2048, 512,
            0, 0, 0, 0, 0, 1, 0, 0, 1.f, fc1_b, nullptr, 0, 0));

    // 11. out = h1 @ fc2 + b2 + res : M=8192, N=512, K=2048
    gemm_mma<2><<<dim3(4,64,1), 256, SM_TOTAL>>>(
        mkP(h1, fc2T, out, 2048, 2048, 512, 2048,
            0, 0, 0, 0, 0, 1, 0, 0, 1.f, fc2_b, res, 512, 0));
}

// round 7
// speedup vs baseline: 4.2531x; 1.0327x over previous
#include <cuda_runtime.h>
#include <math.h>
#include <stdint.h>

#define NB 8
#define NTOK 1024
#define CC2 512
#define KVD 1792
#define NH 4
#define NMAPS (NB*NH)          // 32
#define MAPELEMS (CC2*KVD)     // 917504
#define NPART (NMAPS*56)       // 56 tiles per map (14 x 4)

// ---------------- scratch ----------------
__device__ __align__(128) float g_X   [NB*NTOK*KVD];
__device__ __align__(128) float g_XT  [NB*KVD*NTOK];
__device__ __align__(128) float g_cx2 [NB*NTOK*CC2];
__device__ __align__(128) float g_c2T [NB*CC2*NTOK];
__device__ __align__(128) float g_Gt  [NB*KVD*CC2];
__device__ __align__(128) float g_T   [NMAPS*CC2*KVD];
__device__ __align__(128) float g_S   [NMAPS*CC2*KVD];
__device__ __align__(128) float g_Mt  [NB*CC2*KVD];
__device__ __align__(128) float g_ctx [NB*NTOK*CC2];
__device__ __align__(128) float g_res [NB*NTOK*CC2];
__device__ __align__(128) float g_x2  [NB*NTOK*CC2];
__device__ __align__(128) float g_h1  [NB*NTOK*CC2*4];
__device__ __align__(128) float g_WqT [NH*CC2*CC2];
__device__ __align__(128) float g_WkT [NH*KVD*KVD];
__device__ __align__(128) float g_WoutT[CC2*CC2];
__device__ __align__(128) float g_fc1T[CC2*4*CC2];
__device__ __align__(128) float g_fc2T[CC2*CC2*4];
__device__ __align__(128) float g_part[NPART*2];

// ---------------- helpers ----------------
__device__ __forceinline__ uint32_t smem_u32(const void* p) {
    uint32_t a;
    asm("{ .reg .u64 t; cvta.to.shared.u64 t, %1; cvt.u32.u64 %0, t; }" : "=r"(a) : "l"(p));
    return a;
}
#define CP_ASYNC16(sa, ga) \
    asm volatile("cp.async.cg.shared.global [%0], [%1], 16;" :: "r"(sa), "l"(ga) : "memory")
#define CP_COMMIT() asm volatile("cp.async.commit_group;" ::: "memory")
#define CP_WAIT2()  asm volatile("cp.async.wait_group 2;" ::: "memory")

__device__ __forceinline__ void mma_tf32(float* c, const uint32_t* a, const uint32_t* b) {
    asm volatile(
        "mma.sync.aligned.m16n8k8.row.col.f32.tf32.tf32.f32 "
        "{%0,%1,%2,%3}, {%4,%5,%6,%7}, {%8,%9}, {%0,%1,%2,%3};"
        : "+f"(c[0]), "+f"(c[1]), "+f"(c[2]), "+f"(c[3])
        : "r"(a[0]), "r"(a[1]), "r"(a[2]), "r"(a[3]), "r"(b[0]), "r"(b[1]));
}

// ---------------- tensor-core GEMM: D[M,N] = alpha * sum_seg A[M,K] @ B[N,K]^T
// CTA tile 128x128, 4 warps in 2x2 grid, warp tile 64x64.
#define BM 128
#define BN 128
#define PAD 36
#define SM_BUF (128*PAD)              // floats per operand buffer
#define NSTAGE 3
#define SM_TOTAL (NSTAGE*2*SM_BUF*4)  // 110592 bytes

struct TCP {
    const float *A, *B; float *C;
    int lda, ldb, ldc, K;
    long sA, sB, sC;
    int aSel, bSel, nseg;
    long segA, segB;
    float alpha;
    const float* bias;
    const float* add; int ldAdd; long sAdd;
    float* part;                // EPI 3: partial stats output
};

// EPI: 0 plain; 1 bias+gelu; 2 (+bias)+add; 3 plain + per-CTA IN partial stats
template <int EPI>
__global__ void __launch_bounds__(128, 2) gemm_mma(TCP p)
{
    extern __shared__ float sm[];
    uint32_t sb = smem_u32(sm);

    int t = threadIdx.x, lane = t & 31, w = t >> 5;
    int z = blockIdx.z;
    int m0 = blockIdx.y * BM, n0 = blockIdx.x * BN;
    int az = p.aSel == 0 ? z : (p.aSel == 1 ? (z & 3) : (z >> 2));
    int bz = p.bSel == 0 ? z : (p.bSel == 1 ? (z & 3) : (z >> 2));
    const float* Ab = p.A + (long)az * p.sA + (size_t)m0 * p.lda;
    const float* Bb = p.B + (long)bz * p.sB + (size_t)n0 * p.ldb;
    float* Cz = p.C + (long)z * p.sC;

    int kIters = p.K >> 5;
    int nIt = kIters * p.nseg;
    int seg = 0, kk = 0;

    // issue loads for a stage; buf in [0, NSTAGE)
    auto issue = [&](int buf) {
        const float* Ag = Ab + (long)seg * p.segA + kk;
        const float* Bg = Bb + (long)seg * p.segB + kk;
        uint32_t da = sb + (2 * buf) * SM_BUF * 4;
        uint32_t db = sb + (2 * buf + 1) * SM_BUF * 4;
        #pragma unroll
        for (int i = 0; i < 8; i++) {
            int task = t + i * 128, row = task >> 3, q = task & 7;
            CP_ASYNC16(da + (row * PAD + q * 4) * 4, Ag + (size_t)row * p.lda + q * 4);
            CP_ASYNC16(db + (row * PAD + q * 4) * 4, Bg + (size_t)row * p.ldb + q * 4);
        }
        CP_COMMIT();
        kk += 32; if (kk == p.K) { kk = 0; seg++; }
    };

    issue(0);
    if (nIt > 1) issue(1);

    int wm = (w >> 1) * 64, wn = (w & 1) * 64;
    float acc[4][8][4] = {};
    int arowL = wm + (lane >> 2), browL = wn + (lane >> 2);

    for (int it = 0; it < nIt; it++) {
        int buf = it % NSTAGE;
        if (it + 2 < nIt) issue((it + 2) % NSTAGE);
        else CP_COMMIT();                 // empty group keeps wait accounting uniform
        CP_WAIT2();
        __syncthreads();

        const uint32_t* Ai = (const uint32_t*)(sm + (2 * buf) * SM_BUF);
        const uint32_t* Bi = (const uint32_t*)(sm + (2 * buf + 1) * SM_BUF);
        #pragma unroll
        for (int ks = 0; ks < 4; ks++) {
            int ac = ks * 8 + (lane & 3);
            uint32_t a[4][4], b[8][2];
            #pragma unroll
            for (int mi = 0; mi < 4; mi++) {
                const uint32_t* p0 = Ai + (size_t)(arowL + mi * 16) * PAD + ac;
                a[mi][0] = p0[0];
                a[mi][2] = p0[4];
                a[mi][1] = p0[8 * PAD];
                a[mi][3] = p0[8 * PAD + 4];
            }
            #pragma unroll
            for (int ni = 0; ni < 8; ni++) {
                const uint32_t* p0 = Bi + (size_t)(browL + ni * 8) * PAD + ac;
                b[ni][0] = p0[0];
                b[ni][1] = p0[4];
            }
            #pragma unroll
            for (int mi = 0; mi < 4; mi++)
                #pragma unroll
                for (int ni = 0; ni < 8; ni++)
                    mma_tf32(acc[mi][ni], a[mi], b[ni]);
        }
        __syncthreads();
    }

    // -------- epilogue --------
    float psum = 0.f, psq = 0.f;
    #pragma unroll
    for (int mi = 0; mi < 4; mi++) {
        #pragma unroll
        for (int ni = 0; ni < 8; ni++) {
            int r0 = m0 + wm + mi * 16 + (lane >> 2);
            int cc = n0 + wn + ni * 8 + (lane & 3) * 2;
            #pragma unroll
            for (int h = 0; h < 2; h++) {
                int gr = r0 + h * 8;
                float v0 = p.alpha * acc[mi][ni][h * 2 + 0];
                float v1 = p.alpha * acc[mi][ni][h * 2 + 1];
                if (EPI == 1) {
                    v0 += p.bias[cc]; v1 += p.bias[cc + 1];
                    v0 = 0.5f * v0 * (1.f + erff(v0 * 0.70710678118654752f));
                    v1 = 0.5f * v1 * (1.f + erff(v1 * 0.70710678118654752f));
                }
                if (EPI == 2) {
                    if (p.bias) { v0 += p.bias[cc]; v1 += p.bias[cc + 1]; }
                    const float* ap = p.add + (long)z * p.sAdd + (size_t)gr * p.ldAdd + cc;
                    float2 av = *(const float2*)ap;
                    v0 += av.x; v1 += av.y;
                }
                if (EPI == 3) { psum += v0 + v1; psq += v0 * v0 + v1 * v1; }
                *(float2*)&Cz[(size_t)gr * p.ldc + cc] = make_float2(v0, v1);
            }
        }
    }
    if (EPI == 3) {
        #pragma unroll
        for (int o = 16; o > 0; o >>= 1) {
            psum += __shfl_down_sync(0xffffffffu, psum, o);
            psq  += __shfl_down_sync(0xffffffffu, psq,  o);
        }
        __syncthreads();
        if (lane == 0) { sm[w] = psum; sm[8 + w] = psq; }
        __syncthreads();
        if (t == 0) {
            float s = 0.f, ss = 0.f;
            #pragma unroll
            for (int i = 0; i < 4; i++) { s += sm[i]; ss += sm[8 + i]; }
            int idx = (z * 4 + blockIdx.y) * 14 + blockIdx.x;
            p.part[idx * 2] = s;
            p.part[idx * 2 + 1] = ss;
        }
    }
}

// ---------------- transpose ----------------
__global__ void __launch_bounds__(256) transpose_kernel(
    const float* __restrict__ in, float* __restrict__ out, int rows, int cols)
{
    __shared__ float tile[32][33];
    long zo = (long)blockIdx.z * rows * cols;
    const float* ip = in + zo;
    float* op = out + zo;
    int c0 = blockIdx.x * 32, r0 = blockIdx.y * 32;
    int tx = threadIdx.x & 31, ty = threadIdx.x >> 5;
    #pragma unroll
    for (int i = 0; i < 4; i++)
        tile[ty + i * 8][tx] = ip[(size_t)(r0 + ty + i * 8) * cols + c0 + tx];
    __syncthreads();
    #pragma unroll
    for (int i = 0; i < 4; i++)
        op[(size_t)(c0 + ty + i * 8) * rows + r0 + tx] = tile[tx][ty + i * 8];
}

// ---------------- elementwise ----------------
__device__ __forceinline__ float blockReduceSum(float v, float* sbuf) {
    #pragma unroll
    for (int o = 16; o > 0; o >>= 1) v += __shfl_down_sync(0xffffffffu, v, o);
    int lane = threadIdx.x & 31, w = threadIdx.x >> 5;
    if (lane == 0) sbuf[w] = v;
    __syncthreads();
    float tot = 0.f;
    #pragma unroll
    for (int i = 0; i < 8; i++) tot += sbuf[i];
    __syncthreads();
    return tot;
}

__global__ void __launch_bounds__(256) ln_all_kernel(
    const float* __restrict__ e1, const float* __restrict__ e2, const float* __restrict__ e3,
    const float* __restrict__ g1, const float* __restrict__ b1,
    const float* __restrict__ ga, const float* __restrict__ ba,
    float* __restrict__ X, float* __restrict__ cx2)
{
    __shared__ float xs[KVD];
    __shared__ float red[8];
    int tok = blockIdx.x, t = threadIdx.x;
    const float* p1 = e1 + (size_t)tok * 256;
    const float* p2 = e2 + (size_t)tok * 512;
    const float* p3 = e3 + (size_t)tok * 1024;
    xs[t] = p1[t];
    xs[256 + t] = p2[t];
    xs[512 + t] = p2[256 + t];
    #pragma unroll
    for (int i = 0; i < 4; i++) xs[768 + t + i * 256] = p3[t + i * 256];
    __syncthreads();
    float s = 0.f, ss = 0.f, s2 = 0.f, ss2 = 0.f;
    for (int i = t; i < KVD; i += 256) { float x = xs[i]; s += x; ss += x * x; }
    for (int i = t; i < 512; i += 256) { float x = xs[256 + i]; s2 += x; ss2 += x * x; }
    s  = blockReduceSum(s,  red);
    ss = blockReduceSum(ss, red);
    s2 = blockReduceSum(s2, red);
    ss2= blockReduceSum(ss2,red);
    float m  = s * (1.f / KVD), r = rsqrtf(ss * (1.f / KVD) - m * m + 1e-6f);
    float m2 = s2 * (1.f / 512.f), r2 = rsqrtf(ss2 * (1.f / 512.f) - m2 * m2 + 1e-6f);
    float* Xo = X + (size_t)tok * KVD;
    float* co = cx2 + (size_t)tok * 512;
    for (int i = t; i < KVD; i += 256) Xo[i] = (xs[i] - m) * r * ga[i] + ba[i];
    for (int i = t; i < 512; i += 256) co[i] = (xs[256 + i] - m2) * r2 * g1[i] + b1[i];
}

__global__ void __launch_bounds__(256) ln512_kernel(
    const float* __restrict__ in, const float* __restrict__ g, const float* __restrict__ b,
    float* __restrict__ out)
{
    __shared__ float red[8];
    int tok = blockIdx.x, t = threadIdx.x;
    const float* p = in + (size_t)tok * 512;
    float x0 = p[t], x1 = p[t + 256];
    float s = blockReduceSum(x0 + x1, red);
    float ss = blockReduceSum(x0 * x0 + x1 * x1, red);
    float m = s * (1.f / 512.f);
    float r = rsqrtf(ss * (1.f / 512.f) - m * m + 1e-6f);
    float* o = out + (size_t)tok * 512;
    o[t] = (x0 - m) * r * g[t] + b[t];
    o[t + 256] = (x1 - m) * r * g[t + 256] + b[t + 256];
}

// softmax over KV; computes rstd from the 56 GEMM-tile partials per map
__global__ void __launch_bounds__(256) softmax_kernel(float* __restrict__ S,
                                                      const float* __restrict__ part)
{
    __shared__ float red[8];
    int row = blockIdx.x, t = threadIdx.x;
    int map = row >> 9;
    float s0 = 0.f, q0 = 0.f;
    const float2* pp = (const float2*)part + map * 56;
    #pragma unroll 8
    for (int i = 0; i < 56; i++) { float2 v = pp[i]; s0 += v.x; q0 += v.y; }
    float invn = 1.f / (float)MAPELEMS;
    float mean = s0 * invn;
    float r = rsqrtf(q0 * invn - mean * mean + 1e-5f);

    float* p = S + (size_t)row * KVD;
    float v[7];
    float mx = -1e30f;
    #pragma unroll
    for (int j = 0; j < 7; j++) { v[j] = p[t + j * 256] * r; mx = fmaxf(mx, v[j]); }
    #pragma unroll
    for (int o = 16; o > 0; o >>= 1) mx = fmaxf(mx, __shfl_xor_sync(0xffffffffu, mx, o));
    int lane = t & 31, w = t >> 5;
    if (lane == 0) red[w] = mx;
    __syncthreads();
    float bm = red[0];
    #pragma unroll
    for (int i = 1; i < 8; i++) bm = fmaxf(bm, red[i]);
    __syncthreads();
    float s = 0.f;
    #pragma unroll
    for (int j = 0; j < 7; j++) { v[j] = expf(v[j] - bm); s += v[j]; }
    s = blockReduceSum(s, red);
    float inv = 1.f / s;
    #pragma unroll
    for (int j = 0; j < 7; j++) p[t + j * 256] = v[j] * inv;
}

// ---------------- host ----------------
static inline TCP mkP(const float* A, const float* B, float* C,
                      int lda, int ldb, int ldc, int K,
                      long sA, long sB, long sC, int aSel, int bSel,
                      int nseg, long segA, long segB, float alpha,
                      const float* bias, const float* add, int ldAdd, long sAdd,
                      float* part = nullptr)
{
    TCP p; p.A = A; p.B = B; p.C = C; p.lda = lda; p.ldb = ldb; p.ldc = ldc; p.K = K;
    p.sA = sA; p.sB = sB; p.sC = sC; p.aSel = aSel; p.bSel = bSel;
    p.nseg = nseg; p.segA = segA; p.segB = segB; p.alpha = alpha;
    p.bias = bias; p.add = add; p.ldAdd = ldAdd; p.sAdd = sAdd; p.part = part;
    return p;
}

extern "C" void kernel_launch(void* const* d_in, const int* in_sizes, int n_in,
                              void* d_out, int out_size)
{
    const float* emb1   = (const float*)d_in[0];
    const float* emb2   = (const float*)d_in[1];
    const float* emb3   = (const float*)d_in[2];
    const float* Wq     = (const float*)d_in[3];
    const float* Wk     = (const float*)d_in[4];
    const float* Wv     = (const float*)d_in[5];
    const float* Wout   = (const float*)d_in[6];
    const float* ln1_g  = (const float*)d_in[7];
    const float* ln1_b  = (const float*)d_in[8];
    const float* lnall_g= (const float*)d_in[9];
    const float* lnall_b= (const float*)d_in[10];
    const float* lnffn_g= (const float*)d_in[11];
    const float* lnffn_b= (const float*)d_in[12];
    const float* fc1_w  = (const float*)d_in[13];
    const float* fc1_b  = (const float*)d_in[14];
    const float* fc2_w  = (const float*)d_in[15];
    const float* fc2_b  = (const float*)d_in[16];
    float* out = (float*)d_out;

    cudaFuncSetAttribute(gemm_mma<0>, cudaFuncAttributeMaxDynamicSharedMemorySize, SM_TOTAL);
    cudaFuncSetAttribute(gemm_mma<1>, cudaFuncAttributeMaxDynamicSharedMemorySize, SM_TOTAL);
    cudaFuncSetAttribute(gemm_mma<2>, cudaFuncAttributeMaxDynamicSharedMemorySize, SM_TOTAL);
    cudaFuncSetAttribute(gemm_mma<3>, cudaFuncAttributeMaxDynamicSharedMemorySize, SM_TOTAL);

    float *X,*XT,*cx2,*c2T,*Gt,*T,*S,*Mt,*ctx,*res,*x2,*h1;
    float *WqT,*WkT,*WoutT,*fc1T,*fc2T,*part;
    cudaGetSymbolAddress((void**)&X,    g_X);
    cudaGetSymbolAddress((void**)&XT,   g_XT);
    cudaGetSymbolAddress((void**)&cx2,  g_cx2);
    cudaGetSymbolAddress((void**)&c2T,  g_c2T);
    cudaGetSymbolAddress((void**)&Gt,   g_Gt);
    cudaGetSymbolAddress((void**)&T,    g_T);
    cudaGetSymbolAddress((void**)&S,    g_S);
    cudaGetSymbolAddress((void**)&Mt,   g_Mt);
    cudaGetSymbolAddress((void**)&ctx,  g_ctx);
    cudaGetSymbolAddress((void**)&res,  g_res);
    cudaGetSymbolAddress((void**)&x2,   g_x2);
    cudaGetSymbolAddress((void**)&h1,   g_h1);
    cudaGetSymbolAddress((void**)&WqT,  g_WqT);
    cudaGetSymbolAddress((void**)&WkT,  g_WkT);
    cudaGetSymbolAddress((void**)&WoutT,g_WoutT);
    cudaGetSymbolAddress((void**)&fc1T, g_fc1T);
    cudaGetSymbolAddress((void**)&fc2T, g_fc2T);
    cudaGetSymbolAddress((void**)&part, g_part);

    const long MAPSZ = (long)CC2 * KVD;
    const float inv_sqrt_kv = 1.f / sqrtf((float)KVD);

    // weight transposes
    transpose_kernel<<<dim3(16,16,4), 256>>>(Wq, WqT, 512, 512);
    transpose_kernel<<<dim3(56,56,4), 256>>>(Wk, WkT, KVD, KVD);
    transpose_kernel<<<dim3(16,16,1), 256>>>(Wout, WoutT, 512, 512);
    transpose_kernel<<<dim3(64,16,1), 256>>>(fc1_w, fc1T, 512, 2048);
    transpose_kernel<<<dim3(16,64,1), 256>>>(fc2_w, fc2T, 2048, 512);

    // 1. LayerNorms + activation transposes
    ln_all_kernel<<<NB*NTOK, 256>>>(emb1, emb2, emb3, ln1_g, ln1_b,
                                    lnall_g, lnall_b, X, cx2);
    transpose_kernel<<<dim3(56,32,8), 256>>>(X, XT, NTOK, KVD);
    transpose_kernel<<<dim3(16,32,8), 256>>>(cx2, c2T, NTOK, 512);

    // 2. Gt[b][j][c] : M=KVD, N=512, K=1024
    gemm_mma<0><<<dim3(4,14,8), 128, SM_TOTAL>>>(
        mkP(XT, c2T, Gt, NTOK, NTOK, 512, NTOK,
            (long)KVD*NTOK, (long)512*NTOK, (long)KVD*512, 0, 0,
            1, 0, 0, 1.f, nullptr, nullptr, 0, 0));

    // 3. T[z][d][j] : M=512, N=KVD, K=512
    gemm_mma<0><<<dim3(14,4,32), 128, SM_TOTAL>>>(
        mkP(WqT, Gt, T, 512, 512, KVD, 512,
            (long)512*512, (long)KVD*512, MAPSZ, 1, 2,
            1, 0, 0, 1.f, nullptr, nullptr, 0, 0));

    // 4. S[z][d][k'] : M=512, N=KVD, K=KVD ; fused IN partial stats
    gemm_mma<3><<<dim3(14,4,32), 128, SM_TOTAL>>>(
        mkP(T, WkT, S, KVD, KVD, KVD, KVD,
            MAPSZ, (long)KVD*KVD, MAPSZ, 0, 1,
            1, 0, 0, inv_sqrt_kv, nullptr, nullptr, 0, 0, part));

    // 5. probs = softmax(rstd * S) — rstd folded in from partials
    softmax_kernel<<<NMAPS*512, 256>>>(S, part);

    // 6. Mt[b][c][j] : M=512, N=KVD, 4 segs over h
    gemm_mma<0><<<dim3(14,4,8), 128, SM_TOTAL>>>(
        mkP(S, Wv, Mt, KVD, KVD, KVD, KVD,
            4*MAPSZ, 0, (long)512*KVD, 0, 0,
            4, MAPSZ, (long)KVD*KVD, 0.25f, nullptr, nullptr, 0, 0));

    // 7. ctx[b][t][c] : M=1024, N=512, K=KVD
    gemm_mma<0><<<dim3(4,8,8), 128, SM_TOTAL>>>(
        mkP(X, Mt, ctx, KVD, KVD, 512, KVD,
            (long)NTOK*KVD, (long)512*KVD, (long)NTOK*512, 0, 0,
            1, 0, 0, 1.f, nullptr, nullptr, 0, 0));

    // 8. res = ctx @ Wout + emb2 : M=8192, N=512, K=512
    gemm_mma<2><<<dim3(4,64,1), 128, SM_TOTAL>>>(
        mkP(ctx, WoutT, res, 512, 512, 512, 512,
            0, 0, 0, 0, 0, 1, 0, 0, 1.f, nullptr, emb2, 512, 0));

    // 9. x2 = LN(res)
    ln512_kernel<<<NB*NTOK, 256>>>(res, lnffn_g, lnffn_b, x2);

    // 10. h1 = gelu(x2 @ fc1 + b1) : M=8192, N=2048, K=512
    gemm_mma<1><<<dim3(16,64,1), 128, SM_TOTAL>>>(
        mkP(x2, fc1T, h1, 512, 512, 2048, 512,
            0, 0, 0, 0, 0, 1, 0, 0, 1.f, fc1_b, nullptr, 0, 0));

    // 11. out = h1 @ fc2 + b2 + res : M=8192, N=512, K=2048
    gemm_mma<2><<<dim3(4,64,1), 128, SM_TOTAL>>>(
        mkP(h1, fc2T, out, 2048, 2048, 512, 2048,
            0, 0, 0, 0, 0, 1, 0, 0, 1.f, fc2_b, res, 512, 0));
}